// round 2
// baseline (speedup 1.0000x reference)
#include <cuda_runtime.h>
#include <math.h>

// Problem: MADE/IAF layer.
//   zp = z[:, perm]
//   h  = relu(zp @ (W1*M1) + b1)          M=4096 K=1024 N=4096
//   r  = h @ (W2*M2) + b2                 M=4096 K=4096 N=2048
//   mu = r[:, :D], log_s = r[:, D:]
//   x  = zp*exp(log_s)+mu ; out_x[:, perm[d]] = x[:, d] ; log_det = sum(log_s)
// Masks are index functions:
//   M1[d,h] = (h % (D-1)) >= d
//   M2[h,o] = (o % D)     >  (h % (D-1))

#define BM 128
#define BN 128
#define BK 16
#define TM 8
#define TN 8
#define NTHREADS 256

// Scratch (allocation-free rule: __device__ globals)
__device__ float g_zp[4096L * 1024];   // 16.8 MB
__device__ float g_h [4096L * 4096];   // 67.1 MB
__device__ float g_res[4096L * 2048];  // 33.6 MB

__global__ void gather_zp_kernel(const float* __restrict__ z,
                                 const int* __restrict__ perm,
                                 int Brows, int D) {
    int idx = blockIdx.x * blockDim.x + threadIdx.x;
    int total = Brows * D;
    if (idx < total) {
        int b = idx / D;
        int d = idx - b * D;
        g_zp[idx] = z[(size_t)b * D + perm[d]];
    }
}

// MODE 1: A=g_zp, Bw=W1, mask1, bias+relu, C=g_h
// MODE 2: A=g_h,  Bw=W2, mask2, bias,      C=g_res
template <int MODE>
__global__ void __launch_bounds__(NTHREADS)
gemm_kernel(const float* __restrict__ Bw, const float* __restrict__ bias,
            int M, int N, int K, int D)
{
    const float* __restrict__ A = (MODE == 1) ? g_zp : g_h;
    float* __restrict__ C       = (MODE == 1) ? g_h  : g_res;

    __shared__ float As[2][BK][BM + 4];
    __shared__ float Bs[2][BK][BN];

    const int tid  = threadIdx.x;
    const int row0 = blockIdx.y * BM;
    const int col0 = blockIdx.x * BN;

    // global-load mappings
    const int a_row = tid >> 2;          // 0..63, second pass +64
    const int a_col = (tid & 3) * 4;     // 0,4,8,12
    const int b_row = tid >> 5;          // 0..7, second pass +8
    const int b_col = (tid & 31) * 4;    // 0..124

    const int Dm1 = D - 1;

    // per-thread fixed column mask keys for Bw loads
    int nkey[4];
#pragma unroll
    for (int i = 0; i < 4; i++) {
        int n = col0 + b_col + i;
        nkey[i] = (MODE == 1) ? (n % Dm1) : (n % D);
    }

    const float* Aptr = A + (size_t)row0 * K;
    const float* Bptr = Bw + col0;

    const int tcol = (tid & 15) * TN;
    const int trow = (tid >> 4) * TM;

    float acc[TM][TN];
#pragma unroll
    for (int i = 0; i < TM; i++)
#pragma unroll
        for (int j = 0; j < TN; j++) acc[i][j] = 0.f;

    const int nTiles = K / BK;

    // ---- load tile 0 ----
    {
        float4 a0 = *(const float4*)(Aptr + (size_t)a_row * K + a_col);
        float4 a1 = *(const float4*)(Aptr + (size_t)(a_row + 64) * K + a_col);
        As[0][a_col + 0][a_row] = a0.x; As[0][a_col + 1][a_row] = a0.y;
        As[0][a_col + 2][a_row] = a0.z; As[0][a_col + 3][a_row] = a0.w;
        As[0][a_col + 0][a_row + 64] = a1.x; As[0][a_col + 1][a_row + 64] = a1.y;
        As[0][a_col + 2][a_row + 64] = a1.z; As[0][a_col + 3][a_row + 64] = a1.w;

        float4 b0 = *(const float4*)(Bptr + (size_t)b_row * N + b_col);
        float4 b1 = *(const float4*)(Bptr + (size_t)(b_row + 8) * N + b_col);
        int k0 = b_row, k1 = b_row + 8;
        int km0 = (MODE == 2) ? (k0 % Dm1) : k0;
        int km1 = (MODE == 2) ? (k1 % Dm1) : k1;
        float* d0 = &Bs[0][b_row][b_col];
        float* d1 = &Bs[0][b_row + 8][b_col];
        if (MODE == 1) {
            d0[0] = (nkey[0] >= km0) ? b0.x : 0.f; d0[1] = (nkey[1] >= km0) ? b0.y : 0.f;
            d0[2] = (nkey[2] >= km0) ? b0.z : 0.f; d0[3] = (nkey[3] >= km0) ? b0.w : 0.f;
            d1[0] = (nkey[0] >= km1) ? b1.x : 0.f; d1[1] = (nkey[1] >= km1) ? b1.y : 0.f;
            d1[2] = (nkey[2] >= km1) ? b1.z : 0.f; d1[3] = (nkey[3] >= km1) ? b1.w : 0.f;
        } else {
            d0[0] = (nkey[0] > km0) ? b0.x : 0.f; d0[1] = (nkey[1] > km0) ? b0.y : 0.f;
            d0[2] = (nkey[2] > km0) ? b0.z : 0.f; d0[3] = (nkey[3] > km0) ? b0.w : 0.f;
            d1[0] = (nkey[0] > km1) ? b1.x : 0.f; d1[1] = (nkey[1] > km1) ? b1.y : 0.f;
            d1[2] = (nkey[2] > km1) ? b1.z : 0.f; d1[3] = (nkey[3] > km1) ? b1.w : 0.f;
        }
    }
    __syncthreads();

    float4 a_ld0, a_ld1, b_ld0, b_ld1;
    for (int t = 0; t < nTiles; t++) {
        const int cur = t & 1;
        const bool has_next = (t + 1 < nTiles);
        if (has_next) {
            int kk = (t + 1) * BK;
            a_ld0 = *(const float4*)(Aptr + (size_t)a_row * K + kk + a_col);
            a_ld1 = *(const float4*)(Aptr + (size_t)(a_row + 64) * K + kk + a_col);
            b_ld0 = *(const float4*)(Bptr + (size_t)(kk + b_row) * N + b_col);
            b_ld1 = *(const float4*)(Bptr + (size_t)(kk + b_row + 8) * N + b_col);
        }

#pragma unroll
        for (int k = 0; k < BK; k++) {
            float4 a0 = *(const float4*)&As[cur][k][trow];
            float4 a1 = *(const float4*)&As[cur][k][trow + 4];
            float4 b0 = *(const float4*)&Bs[cur][k][tcol];
            float4 b1 = *(const float4*)&Bs[cur][k][tcol + 4];
            float af[TM] = {a0.x, a0.y, a0.z, a0.w, a1.x, a1.y, a1.z, a1.w};
            float bf[TN] = {b0.x, b0.y, b0.z, b0.w, b1.x, b1.y, b1.z, b1.w};
#pragma unroll
            for (int i = 0; i < TM; i++)
#pragma unroll
                for (int j = 0; j < TN; j++)
                    acc[i][j] = fmaf(af[i], bf[j], acc[i][j]);
        }

        if (has_next) {
            const int nxt = cur ^ 1;
            int kk = (t + 1) * BK;
            As[nxt][a_col + 0][a_row] = a_ld0.x; As[nxt][a_col + 1][a_row] = a_ld0.y;
            As[nxt][a_col + 2][a_row] = a_ld0.z; As[nxt][a_col + 3][a_row] = a_ld0.w;
            As[nxt][a_col + 0][a_row + 64] = a_ld1.x; As[nxt][a_col + 1][a_row + 64] = a_ld1.y;
            As[nxt][a_col + 2][a_row + 64] = a_ld1.z; As[nxt][a_col + 3][a_row + 64] = a_ld1.w;

            int k0 = kk + b_row, k1 = kk + b_row + 8;
            int km0 = (MODE == 2) ? (k0 % Dm1) : k0;
            int km1 = (MODE == 2) ? (k1 % Dm1) : k1;
            float* d0 = &Bs[nxt][b_row][b_col];
            float* d1 = &Bs[nxt][b_row + 8][b_col];
            if (MODE == 1) {
                d0[0] = (nkey[0] >= km0) ? b_ld0.x : 0.f; d0[1] = (nkey[1] >= km0) ? b_ld0.y : 0.f;
                d0[2] = (nkey[2] >= km0) ? b_ld0.z : 0.f; d0[3] = (nkey[3] >= km0) ? b_ld0.w : 0.f;
                d1[0] = (nkey[0] >= km1) ? b_ld1.x : 0.f; d1[1] = (nkey[1] >= km1) ? b_ld1.y : 0.f;
                d1[2] = (nkey[2] >= km1) ? b_ld1.z : 0.f; d1[3] = (nkey[3] >= km1) ? b_ld1.w : 0.f;
            } else {
                d0[0] = (nkey[0] > km0) ? b_ld0.x : 0.f; d0[1] = (nkey[1] > km0) ? b_ld0.y : 0.f;
                d0[2] = (nkey[2] > km0) ? b_ld0.z : 0.f; d0[3] = (nkey[3] > km0) ? b_ld0.w : 0.f;
                d1[0] = (nkey[0] > km1) ? b_ld1.x : 0.f; d1[1] = (nkey[1] > km1) ? b_ld1.y : 0.f;
                d1[2] = (nkey[2] > km1) ? b_ld1.z : 0.f; d1[3] = (nkey[3] > km1) ? b_ld1.w : 0.f;
            }
            __syncthreads();
        }
    }

    // epilogue: bias (+ relu for MODE 1)
#pragma unroll
    for (int i = 0; i < TM; i++) {
        int r = row0 + trow + i;
#pragma unroll
        for (int j = 0; j < TN; j += 4) {
            int c = col0 + tcol + j;
            float4 v;
            v.x = acc[i][j + 0] + bias[c + 0];
            v.y = acc[i][j + 1] + bias[c + 1];
            v.z = acc[i][j + 2] + bias[c + 2];
            v.w = acc[i][j + 3] + bias[c + 3];
            if (MODE == 1) {
                v.x = fmaxf(v.x, 0.f); v.y = fmaxf(v.y, 0.f);
                v.z = fmaxf(v.z, 0.f); v.w = fmaxf(v.w, 0.f);
            }
            *(float4*)(C + (size_t)r * N + c) = v;
        }
    }
}

__global__ void finish_kernel(const int* __restrict__ perm,
                              float* __restrict__ out,
                              int Brows, int D, int out_size)
{
    int b = blockIdx.x;
    int tid = threadIdx.x;
    const float* mu = g_res + (size_t)b * 2 * D;
    const float* ls = mu + D;
    const float* zp = g_zp + (size_t)b * D;

    float partial = 0.f;
    for (int d = tid; d < D; d += blockDim.x) {
        float l = ls[d];
        float x = zp[d] * expf(l) + mu[d];
        out[(size_t)b * D + perm[d]] = x;  // out_x[b, perm[d]] = x[b, d]
        partial += l;
    }

    __shared__ float red[256];
    red[tid] = partial;
    __syncthreads();
    for (int s = 128; s > 0; s >>= 1) {
        if (tid < s) red[tid] += red[tid + s];
        __syncthreads();
    }
    if (tid == 0 && out_size >= Brows * D + Brows)
        out[(size_t)Brows * D + b] = red[0];
}

extern "C" void kernel_launch(void* const* d_in, const int* in_sizes, int n_in,
                              void* d_out, int out_size)
{
    const float* z   = (const float*)d_in[0];
    const float* W1  = (const float*)d_in[1];
    const float* b1  = (const float*)d_in[2];
    const float* W2  = (const float*)d_in[3];
    const float* b2  = (const float*)d_in[4];
    const int*  perm = (const int*)d_in[5];

    const int D     = in_sizes[5];          // 1024
    const int H     = in_sizes[2];          // 4096
    const int Brows = in_sizes[0] / D;      // 4096
    const int N2    = in_sizes[4];          // 2048

    float* out = (float*)d_out;

    gather_zp_kernel<<<(Brows * D + 255) / 256, 256>>>(z, perm, Brows, D);

    dim3 g1(H / BN, Brows / BM);
    gemm_kernel<1><<<g1, NTHREADS>>>(W1, b1, Brows, H, D, D);

    dim3 g2(N2 / BN, Brows / BM);
    gemm_kernel<2><<<g2, NTHREADS>>>(W2, b2, Brows, N2, H, D);

    finish_kernel<<<Brows, 256>>>(perm, out, Brows, D, out_size);
}

// round 5
// speedup vs baseline: 2.6212x; 2.6212x over previous
#include <cuda_runtime.h>
#include <math.h>
#include <stdint.h>

// MADE/IAF layer via per-warp tf32 mma.sync (compute_103-safe; tcgen05 is
// arch-suffix-gated and this harness emits plain compute_103 PTX).
//   zp = z[:, perm]
//   h  = relu(zp @ (W1*M1) + b1)          M=4096 K=1024 N=4096
//   r  = h @ (W2*M2) + b2                 M=4096 K=4096 N=2048
//   x  = zp*exp(log_s)+mu ; scatter by perm ; log_det = sum(log_s)
// Masks (index functions, fused into B staging):
//   M1[d,h] = (h % (D-1)) >= d
//   M2[h,o] = (o % D)     >  (h % (D-1))

#define BM 128
#define BN 128
#define BK 32
#define NTH 256
#define SMEM_BYTES (4 * 16384)   // As0,Bs0,As1,Bs1 (16KB each)

__device__ float g_zp[4096L * 1024];   // 16.8 MB
__device__ float g_h [4096L * 4096];   // 67.1 MB
__device__ float g_res[4096L * 2048];  // 33.6 MB

__device__ __forceinline__ uint32_t tf32u(float x) {
    uint32_t y; asm("cvt.rna.tf32.f32 %0, %1;" : "=r"(y) : "f"(x)); return y;
}
__device__ __forceinline__ void mma8(float* d,
                                     uint32_t a0, uint32_t a1, uint32_t a2, uint32_t a3,
                                     uint32_t b0, uint32_t b1) {
    asm volatile(
        "mma.sync.aligned.m16n8k8.row.col.f32.tf32.tf32.f32 "
        "{%0,%1,%2,%3}, {%4,%5,%6,%7}, {%8,%9}, {%0,%1,%2,%3};"
        : "+f"(d[0]), "+f"(d[1]), "+f"(d[2]), "+f"(d[3])
        : "r"(a0), "r"(a1), "r"(a2), "r"(a3), "r"(b0), "r"(b1));
}
// swizzled smem byte offset for element (k, x) of a [BK][128] fp32 tile
__device__ __forceinline__ uint32_t swz(int k, int x) {
    return (uint32_t)(((k << 7) + (x ^ ((((k & 3) ^ ((k >> 2) & 3))) << 3))) << 2);
}
__device__ __forceinline__ uint32_t lds32(const char* p) {
    return *(const uint32_t*)p;
}

__global__ void gather_zp_kernel(const float* __restrict__ z,
                                 const int* __restrict__ perm,
                                 int Brows, int D) {
    int idx = blockIdx.x * blockDim.x + threadIdx.x;
    if (idx < Brows * D) {
        int b = idx / D;
        int d = idx - b * D;
        g_zp[idx] = z[(size_t)b * D + perm[d]];
    }
}

// MODE 1: A=g_zp, Bw=W1, mask1, bias+relu, C=g_h
// MODE 2: A=g_h,  Bw=W2, mask2, bias,      C=g_res
template <int MODE>
__global__ void __launch_bounds__(NTH, 1)
gemm_mma(const float* __restrict__ Bw, const float* __restrict__ bias,
         int N, int K, int D)
{
    const float* __restrict__ A = (MODE == 1) ? g_zp : g_h;
    float* __restrict__ C       = (MODE == 1) ? g_h  : g_res;

    extern __shared__ char sm[];
    // buffers: As at buf*32768, Bs at buf*32768 + 16384

    const int tid  = threadIdx.x;
    const int wid  = tid >> 5;
    const int lane = tid & 31;
    const int gq   = lane >> 2;   // groupID
    const int tq   = lane & 3;    // thread-in-group
    const int row0 = blockIdx.x * BM;
    const int col0 = blockIdx.y * BN;
    const int Dm1  = D - 1;

    const int mwarp = (wid & 1) * 64;   // 2 warp-rows of 64
    const int nwarp = (wid >> 1) * 32;  // 4 warp-cols of 32

    // ---- staging maps ----
    // A: fa = tid + i*256 (0..1023): q = fa&7 (k0=4q), m = fa>>3. Coalesced LDG
    //    (8 lanes cover 32 consecutive k of one row). 4 scattered STS.32.
    int aq[4], am[4]; const float* aglob[4]; uint32_t aoff[4][4];
    // B: fb = tid + i*256: k = fb>>5, n0 = (fb&31)*4. Coalesced LDG + STS.128.
    int bk[4], bn0[4]; const float* bglob[4]; uint32_t boff[4]; int key0[4];
#pragma unroll
    for (int i = 0; i < 4; i++) {
        int fa = tid + i * NTH;
        aq[i] = fa & 7;  am[i] = fa >> 3;
        aglob[i] = A + (size_t)(row0 + am[i]) * K + aq[i] * 4;
#pragma unroll
        for (int j = 0; j < 4; j++)
            aoff[i][j] = swz(4 * aq[i] + j, am[i]);

        int fb = tid + i * NTH;
        bk[i] = fb >> 5;  bn0[i] = (fb & 31) * 4;
        bglob[i] = Bw + (size_t)bk[i] * N + col0 + bn0[i];
        boff[i] = swz(bk[i], bn0[i]);
        int c = col0 + bn0[i];
        key0[i] = (MODE == 1) ? (c % Dm1) : (c % D);
    }

    float acc[4][4][4];
#pragma unroll
    for (int mt = 0; mt < 4; mt++)
#pragma unroll
        for (int nt = 0; nt < 4; nt++)
#pragma unroll
            for (int e = 0; e < 4; e++) acc[mt][nt][e] = 0.f;

    const int nT = K / BK;

    // ---- stage tile 0 ----
    {
        char* as = sm; char* bs = sm + 16384;
#pragma unroll
        for (int i = 0; i < 4; i++) {
            float4 v = *(const float4*)(aglob[i]);
            *(uint32_t*)(as + aoff[i][0]) = tf32u(v.x);
            *(uint32_t*)(as + aoff[i][1]) = tf32u(v.y);
            *(uint32_t*)(as + aoff[i][2]) = tf32u(v.z);
            *(uint32_t*)(as + aoff[i][3]) = tf32u(v.w);
        }
#pragma unroll
        for (int i = 0; i < 4; i++) {
            float4 v = *(const float4*)(bglob[i]);
            int kg = bk[i];
            int km = (MODE == 1) ? kg : (kg % Dm1);
            uint4 u;
            int ky;
            ky = key0[i] + 0; if (MODE == 1 && ky >= Dm1) ky -= Dm1;
            u.x = ((MODE == 1) ? (ky >= km) : (ky > km)) ? tf32u(v.x) : 0u;
            ky = key0[i] + 1; if (MODE == 1 && ky >= Dm1) ky -= Dm1;
            u.y = ((MODE == 1) ? (ky >= km) : (ky > km)) ? tf32u(v.y) : 0u;
            ky = key0[i] + 2; if (MODE == 1 && ky >= Dm1) ky -= Dm1;
            u.z = ((MODE == 1) ? (ky >= km) : (ky > km)) ? tf32u(v.z) : 0u;
            ky = key0[i] + 3; if (MODE == 1 && ky >= Dm1) ky -= Dm1;
            u.w = ((MODE == 1) ? (ky >= km) : (ky > km)) ? tf32u(v.w) : 0u;
            *(uint4*)(bs + boff[i]) = u;
        }
    }
    __syncthreads();

    for (int t = 0; t < nT; t++) {
        const int buf = t & 1;
        const bool more = (t + 1 < nT);
        float4 apre[4], bpre[4];
        if (more) {
#pragma unroll
            for (int i = 0; i < 4; i++)
                apre[i] = *(const float4*)(aglob[i] + (t + 1) * BK);
#pragma unroll
            for (int i = 0; i < 4; i++)
                bpre[i] = *(const float4*)(bglob[i] + (size_t)(t + 1) * BK * N);
        }

        // ---- compute on buffer buf ----
        const char* as = sm + buf * 32768;
        const char* bs = as + 16384;
#pragma unroll
        for (int ks = 0; ks < 4; ks++) {
            const int k0 = ks * 8 + tq;
            uint32_t af[4][4];
#pragma unroll
            for (int mt = 0; mt < 4; mt++) {
                int m = mwarp + mt * 16 + gq;
                af[mt][0] = lds32(as + swz(k0,     m));
                af[mt][1] = lds32(as + swz(k0,     m + 8));
                af[mt][2] = lds32(as + swz(k0 + 4, m));
                af[mt][3] = lds32(as + swz(k0 + 4, m + 8));
            }
            uint32_t bf[4][2];
#pragma unroll
            for (int nt = 0; nt < 4; nt++) {
                int n = nwarp + nt * 8 + gq;
                bf[nt][0] = lds32(bs + swz(k0,     n));
                bf[nt][1] = lds32(bs + swz(k0 + 4, n));
            }
#pragma unroll
            for (int mt = 0; mt < 4; mt++)
#pragma unroll
                for (int nt = 0; nt < 4; nt++)
                    mma8(acc[mt][nt], af[mt][0], af[mt][1], af[mt][2], af[mt][3],
                         bf[nt][0], bf[nt][1]);
        }

        if (more) {
            char* asw = sm + (buf ^ 1) * 32768;
            char* bsw = asw + 16384;
#pragma unroll
            for (int i = 0; i < 4; i++) {
                *(uint32_t*)(asw + aoff[i][0]) = tf32u(apre[i].x);
                *(uint32_t*)(asw + aoff[i][1]) = tf32u(apre[i].y);
                *(uint32_t*)(asw + aoff[i][2]) = tf32u(apre[i].z);
                *(uint32_t*)(asw + aoff[i][3]) = tf32u(apre[i].w);
            }
#pragma unroll
            for (int i = 0; i < 4; i++) {
                int kg = (t + 1) * BK + bk[i];
                int km = (MODE == 1) ? kg : (kg % Dm1);
                uint4 u;
                int ky;
                ky = key0[i] + 0; if (MODE == 1 && ky >= Dm1) ky -= Dm1;
                u.x = ((MODE == 1) ? (ky >= km) : (ky > km)) ? tf32u(bpre[i].x) : 0u;
                ky = key0[i] + 1; if (MODE == 1 && ky >= Dm1) ky -= Dm1;
                u.y = ((MODE == 1) ? (ky >= km) : (ky > km)) ? tf32u(bpre[i].y) : 0u;
                ky = key0[i] + 2; if (MODE == 1 && ky >= Dm1) ky -= Dm1;
                u.z = ((MODE == 1) ? (ky >= km) : (ky > km)) ? tf32u(bpre[i].z) : 0u;
                ky = key0[i] + 3; if (MODE == 1 && ky >= Dm1) ky -= Dm1;
                u.w = ((MODE == 1) ? (ky >= km) : (ky > km)) ? tf32u(bpre[i].w) : 0u;
                *(uint4*)(bsw + boff[i]) = u;
            }
            __syncthreads();
        }
    }

    // ---- epilogue: acc -> bias(+relu) -> C ----
#pragma unroll
    for (int mt = 0; mt < 4; mt++) {
        int r0 = row0 + mwarp + mt * 16 + gq;
#pragma unroll
        for (int nt = 0; nt < 4; nt++) {
            int c = col0 + nwarp + nt * 8 + 2 * tq;
            float bx = bias[c], by = bias[c + 1];
            float2 v0, v1;
            v0.x = acc[mt][nt][0] + bx;  v0.y = acc[mt][nt][1] + by;
            v1.x = acc[mt][nt][2] + bx;  v1.y = acc[mt][nt][3] + by;
            if (MODE == 1) {
                v0.x = fmaxf(v0.x, 0.f); v0.y = fmaxf(v0.y, 0.f);
                v1.x = fmaxf(v1.x, 0.f); v1.y = fmaxf(v1.y, 0.f);
            }
            *(float2*)(C + (size_t)r0 * N + c)       = v0;
            *(float2*)(C + (size_t)(r0 + 8) * N + c) = v1;
        }
    }
}

__global__ void finish_kernel(const int* __restrict__ perm,
                              float* __restrict__ out,
                              int Brows, int D, int out_size)
{
    int b = blockIdx.x;
    int tid = threadIdx.x;
    const float* mu = g_res + (size_t)b * 2 * D;
    const float* ls = mu + D;
    const float* zp = g_zp + (size_t)b * D;

    float partial = 0.f;
    for (int d = tid; d < D; d += blockDim.x) {
        float l = ls[d];
        float x = zp[d] * expf(l) + mu[d];
        out[(size_t)b * D + perm[d]] = x;
        partial += l;
    }

    __shared__ float red[256];
    red[tid] = partial;
    __syncthreads();
    for (int s = 128; s > 0; s >>= 1) {
        if (tid < s) red[tid] += red[tid + s];
        __syncthreads();
    }
    if (tid == 0 && out_size >= Brows * D + Brows)
        out[(size_t)Brows * D + b] = red[0];
}

extern "C" void kernel_launch(void* const* d_in, const int* in_sizes, int n_in,
                              void* d_out, int out_size)
{
    const float* z   = (const float*)d_in[0];
    const float* W1  = (const float*)d_in[1];
    const float* b1  = (const float*)d_in[2];
    const float* W2  = (const float*)d_in[3];
    const float* b2  = (const float*)d_in[4];
    const int*  perm = (const int*)d_in[5];

    const int D     = in_sizes[5];          // 1024
    const int H     = in_sizes[2];          // 4096
    const int Brows = in_sizes[0] / D;      // 4096
    const int N2    = in_sizes[4];          // 2048

    float* out = (float*)d_out;

    cudaFuncSetAttribute(gemm_mma<1>, cudaFuncAttributeMaxDynamicSharedMemorySize, SMEM_BYTES);
    cudaFuncSetAttribute(gemm_mma<2>, cudaFuncAttributeMaxDynamicSharedMemorySize, SMEM_BYTES);

    gather_zp_kernel<<<(Brows * D + 255) / 256, 256>>>(z, perm, Brows, D);

    dim3 g1(Brows / BM, H / BN);   // m fast -> weight-tile reuse in L2
    gemm_mma<1><<<g1, NTH, SMEM_BYTES>>>(W1, b1, H, D, D);

    dim3 g2(Brows / BM, N2 / BN);
    gemm_mma<2><<<g2, NTH, SMEM_BYTES>>>(W2, b2, N2, H, D);

    finish_kernel<<<Brows, 256>>>(perm, out, Brows, D, out_size);
}

// round 6
// speedup vs baseline: 3.6137x; 1.3786x over previous
#include <cuda_runtime.h>
#include <math.h>
#include <stdint.h>

// MADE/IAF layer via per-warp tf32 mma.sync (compute_103-safe).
//   zp = z[:, perm]
//   h  = relu(zp @ (W1*M1) + b1)          M=4096 K=1024 N=4096
//   r  = h @ (W2*M2) + b2                 M=4096 K=4096 N=2048
//   x  = zp*exp(log_s)+mu ; scatter by perm ; log_det = sum(log_s)
// Masks (index functions, fused into B staging):
//   M1[d,h] = (h % (D-1)) >= d
//   M2[h,o] = (o % D)     >  (h % (D-1))
// Block-sparsity: k-tiles whose masked B block is entirely zero are skipped.

#define BM 128
#define BN 128
#define BK 32
#define NTH 256
#define SMEM_BYTES (4 * 16384)   // As0,Bs0,As1,Bs1 (16KB each)

__device__ float g_zp[4096L * 1024];   // 16.8 MB
__device__ float g_h [4096L * 4096];   // 67.1 MB
__device__ float g_res[4096L * 2048];  // 33.6 MB

__device__ __forceinline__ uint32_t tf32u(float x) {
    uint32_t y; asm("cvt.rna.tf32.f32 %0, %1;" : "=r"(y) : "f"(x)); return y;
}
__device__ __forceinline__ void mma8(float* d,
                                     uint32_t a0, uint32_t a1, uint32_t a2, uint32_t a3,
                                     uint32_t b0, uint32_t b1) {
    asm volatile(
        "mma.sync.aligned.m16n8k8.row.col.f32.tf32.tf32.f32 "
        "{%0,%1,%2,%3}, {%4,%5,%6,%7}, {%8,%9}, {%0,%1,%2,%3};"
        : "+f"(d[0]), "+f"(d[1]), "+f"(d[2]), "+f"(d[3])
        : "r"(a0), "r"(a1), "r"(a2), "r"(a3), "r"(b0), "r"(b1));
}
// swizzled smem byte offset for element (k, x) of a [BK][128] fp32 tile
__device__ __forceinline__ uint32_t swz(int k, int x) {
    return (uint32_t)(((k << 7) + (x ^ ((((k & 3) ^ ((k >> 2) & 3))) << 3))) << 2);
}
__device__ __forceinline__ uint32_t lds32(const char* p) {
    return *(const uint32_t*)p;
}

__global__ void gather_zp_kernel(const float* __restrict__ z,
                                 const int* __restrict__ perm,
                                 int Brows, int D) {
    int idx = blockIdx.x * blockDim.x + threadIdx.x;
    if (idx < Brows * D) {
        int b = idx / D;
        int d = idx - b * D;
        g_zp[idx] = z[(size_t)b * D + perm[d]];
    }
}

// MODE 1: A=g_zp, Bw=W1, mask1, bias+relu, C=g_h
// MODE 2: A=g_h,  Bw=W2, mask2, bias,      C=g_res
template <int MODE>
__global__ void __launch_bounds__(NTH, 1)
gemm_mma(const float* __restrict__ Bw, const float* __restrict__ bias,
         int N, int K, int D)
{
    const float* __restrict__ A = (MODE == 1) ? g_zp : g_h;
    float* __restrict__ C       = (MODE == 1) ? g_h  : g_res;

    extern __shared__ char sm[];

    const int tid  = threadIdx.x;
    const int wid  = tid >> 5;
    const int lane = tid & 31;
    const int gq   = lane >> 2;
    const int tq   = lane & 3;
    const int row0 = blockIdx.x * BM;
    const int col0 = blockIdx.y * BN;
    const int Dm1  = D - 1;

    const int mwarp = (wid & 1) * 64;
    const int nwarp = (wid >> 1) * 32;

    // ---- tile-skip bounds from mask structure ----
    // GEMM1 keys: c % (D-1) over c in [col0, col0+BN). GEMM2 keys: c % D.
    int maxkey;
    if (MODE == 1) {
        int m0 = col0 % Dm1;
        maxkey = (m0 + BN - 1 >= Dm1) ? (Dm1 - 1) : (m0 + BN - 1);
    } else {
        maxkey = (col0 % D) + BN - 1;   // BN | D alignment: no wrap
    }
    const int nT = K / BK;
    // MODE 1: tile t active iff 32t <= maxkey  -> active prefix [0, nT1)
    const int nT1 = (MODE == 1) ? min(nT, maxkey / BK + 1) : nT;

    // ---- staging maps ----
    int aq[4], am[4]; const float* aglob[4]; uint32_t aoff[4][4];
    int bk[4], bn0[4]; const float* bglob[4]; uint32_t boff[4]; int key0[4];
#pragma unroll
    for (int i = 0; i < 4; i++) {
        int fa = tid + i * NTH;
        aq[i] = fa & 7;  am[i] = fa >> 3;
        aglob[i] = A + (size_t)(row0 + am[i]) * K + aq[i] * 4;
#pragma unroll
        for (int j = 0; j < 4; j++)
            aoff[i][j] = swz(4 * aq[i] + j, am[i]);

        int fb = tid + i * NTH;
        bk[i] = fb >> 5;  bn0[i] = (fb & 31) * 4;
        bglob[i] = Bw + (size_t)bk[i] * N + col0 + bn0[i];
        boff[i] = swz(bk[i], bn0[i]);
        int c = col0 + bn0[i];
        key0[i] = (MODE == 1) ? (c % Dm1) : (c % D);
    }

    float acc[4][4][4];
#pragma unroll
    for (int mt = 0; mt < 4; mt++)
#pragma unroll
        for (int nt = 0; nt < 4; nt++)
#pragma unroll
            for (int e = 0; e < 4; e++) acc[mt][nt][e] = 0.f;

    // ---- staging helpers (macros keep register naming simple) ----
#define STAGE_TILE(TT, AS, BS)                                             \
    {                                                                       \
        char* as_ = (AS); char* bs_ = (BS);                                 \
        _Pragma("unroll")                                                   \
        for (int i = 0; i < 4; i++) {                                       \
            float4 v = *(const float4*)(aglob[i] + (TT) * BK);              \
            *(uint32_t*)(as_ + aoff[i][0]) = tf32u(v.x);                    \
            *(uint32_t*)(as_ + aoff[i][1]) = tf32u(v.y);                    \
            *(uint32_t*)(as_ + aoff[i][2]) = tf32u(v.z);                    \
            *(uint32_t*)(as_ + aoff[i][3]) = tf32u(v.w);                    \
        }                                                                   \
        _Pragma("unroll")                                                   \
        for (int i = 0; i < 4; i++) {                                       \
            float4 v = *(const float4*)(bglob[i] + (size_t)(TT) * BK * N);  \
            int kg = (TT) * BK + bk[i];                                     \
            int km = (MODE == 1) ? kg : (kg % Dm1);                         \
            uint4 u; int ky;                                                \
            ky = key0[i] + 0; if (MODE == 1 && ky >= Dm1) ky -= Dm1;        \
            u.x = ((MODE == 1) ? (ky >= km) : (ky > km)) ? tf32u(v.x) : 0u; \
            ky = key0[i] + 1; if (MODE == 1 && ky >= Dm1) ky -= Dm1;        \
            u.y = ((MODE == 1) ? (ky >= km) : (ky > km)) ? tf32u(v.y) : 0u; \
            ky = key0[i] + 2; if (MODE == 1 && ky >= Dm1) ky -= Dm1;        \
            u.z = ((MODE == 1) ? (ky >= km) : (ky > km)) ? tf32u(v.z) : 0u; \
            ky = key0[i] + 3; if (MODE == 1 && ky >= Dm1) ky -= Dm1;        \
            u.w = ((MODE == 1) ? (ky >= km) : (ky > km)) ? tf32u(v.w) : 0u; \
            *(uint4*)(bs_ + boff[i]) = u;                                   \
        }                                                                   \
    }

#define LOAD_FRAG(KS, AF, BF, AS, BS)                                      \
    {                                                                       \
        const int k0_ = (KS) * 8 + tq;                                      \
        _Pragma("unroll")                                                   \
        for (int mt = 0; mt < 4; mt++) {                                    \
            int m_ = mwarp + mt * 16 + gq;                                  \
            (AF)[mt][0] = lds32((AS) + swz(k0_,     m_));                   \
            (AF)[mt][1] = lds32((AS) + swz(k0_,     m_ + 8));               \
            (AF)[mt][2] = lds32((AS) + swz(k0_ + 4, m_));                   \
            (AF)[mt][3] = lds32((AS) + swz(k0_ + 4, m_ + 8));               \
        }                                                                   \
        _Pragma("unroll")                                                   \
        for (int nt = 0; nt < 4; nt++) {                                    \
            int n_ = nwarp + nt * 8 + gq;                                   \
            (BF)[nt][0] = lds32((BS) + swz(k0_,     n_));                   \
            (BF)[nt][1] = lds32((BS) + swz(k0_ + 4, n_));                   \
        }                                                                   \
    }

    // first tile (t=0 always active in both modes: min key over block >= 0
    // and maxkey >= BN-1 > 0)
    int tcur = 0;
    STAGE_TILE(0, sm, sm + 16384);
    __syncthreads();

    int buf = 0;
    for (;;) {
        // next active tile
        int tn = tcur + 1;
        if (MODE == 1) {
            if (tn >= nT1) tn = nT;
        } else {
            // tile active iff min(k%Dm1 over tile) < maxkey
            while (tn < nT) {
                int r = (tn * BK) % Dm1;
                int minh = (r + BK - 1 > Dm1 - 1) ? 0 : r;   // wrap hits 0
                if (minh < maxkey) break;
                tn++;
            }
        }
        const bool more = (tn < nT);

        float4 apre[4], bpre[4];
        if (more) {
#pragma unroll
            for (int i = 0; i < 4; i++)
                apre[i] = *(const float4*)(aglob[i] + tn * BK);
#pragma unroll
            for (int i = 0; i < 4; i++)
                bpre[i] = *(const float4*)(bglob[i] + (size_t)tn * BK * N);
        }

        // ---- compute on buffer buf with ks-level fragment ping-pong ----
        const char* as = sm + buf * 32768;
        const char* bs = as + 16384;
        uint32_t af[2][4][4], bf[2][4][2];
        LOAD_FRAG(0, af[0], bf[0], as, bs);
#pragma unroll
        for (int ks = 0; ks < 4; ks++) {
            const int cur = ks & 1;
            if (ks < 3) LOAD_FRAG(ks + 1, af[cur ^ 1], bf[cur ^ 1], as, bs);
#pragma unroll
            for (int mt = 0; mt < 4; mt++)
#pragma unroll
                for (int nt = 0; nt < 4; nt++)
                    mma8(acc[mt][nt],
                         af[cur][mt][0], af[cur][mt][1], af[cur][mt][2], af[cur][mt][3],
                         bf[cur][nt][0], bf[cur][nt][1]);
        }

        if (!more) break;

        // stage next active tile into other buffer
        {
            char* asw = sm + (buf ^ 1) * 32768;
            char* bsw = asw + 16384;
#pragma unroll
            for (int i = 0; i < 4; i++) {
                *(uint32_t*)(asw + aoff[i][0]) = tf32u(apre[i].x);
                *(uint32_t*)(asw + aoff[i][1]) = tf32u(apre[i].y);
                *(uint32_t*)(asw + aoff[i][2]) = tf32u(apre[i].z);
                *(uint32_t*)(asw + aoff[i][3]) = tf32u(apre[i].w);
            }
#pragma unroll
            for (int i = 0; i < 4; i++) {
                int kg = tn * BK + bk[i];
                int km = (MODE == 1) ? kg : (kg % Dm1);
                uint4 u; int ky;
                ky = key0[i] + 0; if (MODE == 1 && ky >= Dm1) ky -= Dm1;
                u.x = ((MODE == 1) ? (ky >= km) : (ky > km)) ? tf32u(bpre[i].x) : 0u;
                ky = key0[i] + 1; if (MODE == 1 && ky >= Dm1) ky -= Dm1;
                u.y = ((MODE == 1) ? (ky >= km) : (ky > km)) ? tf32u(bpre[i].y) : 0u;
                ky = key0[i] + 2; if (MODE == 1 && ky >= Dm1) ky -= Dm1;
                u.z = ((MODE == 1) ? (ky >= km) : (ky > km)) ? tf32u(bpre[i].z) : 0u;
                ky = key0[i] + 3; if (MODE == 1 && ky >= Dm1) ky -= Dm1;
                u.w = ((MODE == 1) ? (ky >= km) : (ky > km)) ? tf32u(bpre[i].w) : 0u;
                *(uint4*)(bsw + boff[i]) = u;
            }
        }
        __syncthreads();
        buf ^= 1;
        tcur = tn;
    }

    // ---- epilogue: acc -> bias(+relu) -> C ----
#pragma unroll
    for (int mt = 0; mt < 4; mt++) {
        int r0 = row0 + mwarp + mt * 16 + gq;
#pragma unroll
        for (int nt = 0; nt < 4; nt++) {
            int c = col0 + nwarp + nt * 8 + 2 * tq;
            float bx = bias[c], by = bias[c + 1];
            float2 v0, v1;
            v0.x = acc[mt][nt][0] + bx;  v0.y = acc[mt][nt][1] + by;
            v1.x = acc[mt][nt][2] + bx;  v1.y = acc[mt][nt][3] + by;
            if (MODE == 1) {
                v0.x = fmaxf(v0.x, 0.f); v0.y = fmaxf(v0.y, 0.f);
                v1.x = fmaxf(v1.x, 0.f); v1.y = fmaxf(v1.y, 0.f);
            }
            *(float2*)(C + (size_t)r0 * N + c)       = v0;
            *(float2*)(C + (size_t)(r0 + 8) * N + c) = v1;
        }
    }
#undef STAGE_TILE
#undef LOAD_FRAG
}

__global__ void finish_kernel(const int* __restrict__ perm,
                              float* __restrict__ out,
                              int Brows, int D, int out_size)
{
    int b = blockIdx.x;
    int tid = threadIdx.x;
    const float* mu = g_res + (size_t)b * 2 * D;
    const float* ls = mu + D;
    const float* zp = g_zp + (size_t)b * D;

    float partial = 0.f;
    for (int d = tid; d < D; d += blockDim.x) {
        float l = ls[d];
        float x = zp[d] * expf(l) + mu[d];
        out[(size_t)b * D + perm[d]] = x;
        partial += l;
    }

    __shared__ float red[256];
    red[tid] = partial;
    __syncthreads();
    for (int s = 128; s > 0; s >>= 1) {
        if (tid < s) red[tid] += red[tid + s];
        __syncthreads();
    }
    if (tid == 0 && out_size >= Brows * D + Brows)
        out[(size_t)Brows * D + b] = red[0];
}

extern "C" void kernel_launch(void* const* d_in, const int* in_sizes, int n_in,
                              void* d_out, int out_size)
{
    const float* z   = (const float*)d_in[0];
    const float* W1  = (const float*)d_in[1];
    const float* b1  = (const float*)d_in[2];
    const float* W2  = (const float*)d_in[3];
    const float* b2  = (const float*)d_in[4];
    const int*  perm = (const int*)d_in[5];

    const int D     = in_sizes[5];          // 1024
    const int H     = in_sizes[2];          // 4096
    const int Brows = in_sizes[0] / D;      // 4096
    const int N2    = in_sizes[4];          // 2048

    float* out = (float*)d_out;

    cudaFuncSetAttribute(gemm_mma<1>, cudaFuncAttributeMaxDynamicSharedMemorySize, SMEM_BYTES);
    cudaFuncSetAttribute(gemm_mma<2>, cudaFuncAttributeMaxDynamicSharedMemorySize, SMEM_BYTES);

    gather_zp_kernel<<<(Brows * D + 255) / 256, 256>>>(z, perm, Brows, D);

    dim3 g1(Brows / BM, H / BN);   // m fast -> weight-tile reuse in L2
    gemm_mma<1><<<g1, NTH, SMEM_BYTES>>>(W1, b1, H, D, D);

    dim3 g2(Brows / BM, N2 / BN);
    gemm_mma<2><<<g2, NTH, SMEM_BYTES>>>(W2, b2, N2, H, D);

    finish_kernel<<<Brows, 256>>>(perm, out, Brows, D, out_size);
}